// round 3
// baseline (speedup 1.0000x reference)
#include <cuda_runtime.h>

typedef unsigned long long u64;

#define B_    1024
#define C_    200
#define HW_   225
#define F_    12
#define FR_   6
#define NELEM (C_*HW_)   /* 45000 */
#define BT    4          /* batches per K1 block */

// ---------------- scratch (static device arrays; no allocation) -------------
__device__ float g_kqs[B_*HW_];   // kqs[b][n]
__device__ float g_pp [B_*C_];    // p[b][c] - mean_c(p[b])
__device__ float g_sc [B_*2];     // {Vp, Cpd} per batch

// ---------------- packed-f32 helpers ---------------------------------------
__device__ __forceinline__ u64 pk2(float lo, float hi){
    u64 r; asm("mov.b64 %0, {%1,%2};" : "=l"(r) : "f"(lo), "f"(hi)); return r;
}
__device__ __forceinline__ void upk2(u64 v, float &lo, float &hi){
    asm("mov.b64 {%0,%1}, %2;" : "=f"(lo), "=f"(hi) : "l"(v));
}
__device__ __forceinline__ u64 fma2(u64 a, u64 b, u64 c){
    u64 d; asm("fma.rn.f32x2 %0, %1, %2, %3;" : "=l"(d) : "l"(a), "l"(b), "l"(c));
    return d;
}

// ============================================================================
// K1: block = 4 batches. GEMM k/q/v -> kqs, vm -> softmax -> u -> p,
// plus per-batch LN scalar prep (Vp, Cpd). 4 batches share each weight LDS.
// ============================================================================
__global__ __launch_bounds__(256, 1) void k1_kernel(
    const float* __restrict__ X,
    const float* __restrict__ w11, const float* __restrict__ b11,
    const float* __restrict__ w21, const float* __restrict__ b21,
    const float* __restrict__ w31, const float* __restrict__ b31,
    const float* __restrict__ w41, const float* __restrict__ b41,
    const float* __restrict__ w42, const float* __restrict__ b42)
{
    extern __shared__ __align__(16) unsigned char dynsm[];
    u64  (*wpk)[20]      = (u64 (*)[20])dynsm;                 // [200][20], 32000 B
    float (*v_s)[F_][232] = (float (*)[F_][232])(dynsm + 32000); // [4][12][232], 44544 B

    __shared__ float vm_s[BT][F_], vs_s[BT][F_], u_s[BT][FR_];
    __shared__ float wred[8][4];
    __shared__ float tot[4];

    const int tid = threadIdx.x;
    const int b0  = blockIdx.x * BT;

    // ---- pack weights into smem: wpk[c][j] = (w[2j][c], w[2j+1][c]) --------
    for (int idx = tid; idx < C_*18; idx += 256){
        int c = idx/18, j = idx%18;
        int role = j/6, jj = j%6;
        const float* w = (role==0) ? w11 : (role==1) ? w21 : w31;
        wpk[c][j] = pk2(w[(2*jj)*C_ + c], w[(2*jj+1)*C_ + c]);
    }
    __syncthreads();

    // ---- GEMM: thread owns spatial column n for 4 batches ------------------
    const int n = (tid < HW_) ? tid : (HW_-1);
    const float* xp = X + (size_t)b0*NELEM + n;

    u64 acc[BT][18];
    #pragma unroll
    for (int bt=0;bt<BT;bt++)
        #pragma unroll
        for (int j=0;j<18;j++) acc[bt][j] = 0ULL;

    #pragma unroll 2
    for (int c=0;c<C_;c++){
        u64 xx[BT];
        #pragma unroll
        for (int bt=0;bt<BT;bt++){
            float x = xp[bt*NELEM];
            xx[bt] = pk2(x, x);
        }
        xp += HW_;
        const u64* wr = wpk[c];
        #pragma unroll
        for (int m=0;m<9;m++){
            ulonglong2 w2 = *reinterpret_cast<const ulonglong2*>(wr + 2*m);
            #pragma unroll
            for (int bt=0;bt<BT;bt++){
                acc[bt][2*m]   = fma2(w2.x, xx[bt], acc[bt][2*m]);
                acc[bt][2*m+1] = fma2(w2.y, xx[bt], acc[bt][2*m+1]);
            }
        }
    }

    // ---- epilogue: biases, kqs, store v ------------------------------------
    if (tid < HW_){
        #pragma unroll
        for (int bt=0;bt<BT;bt++){
            float kv[12], qv[12], vv[12];
            #pragma unroll
            for (int j=0;j<6;j++){
                upk2(acc[bt][j],    kv[2*j], kv[2*j+1]);
                upk2(acc[bt][6+j],  qv[2*j], qv[2*j+1]);
                upk2(acc[bt][12+j], vv[2*j], vv[2*j+1]);
            }
            float kqs = 0.f;
            #pragma unroll
            for (int f=0; f<12; f++){
                float kf = kv[f] + b11[f];
                float qf = qv[f] + b21[f];
                kqs = fmaf(kf, qf, kqs);
                v_s[bt][f][n] = vv[f] + b31[f];
            }
            g_kqs[(b0+bt)*HW_ + n] = kqs;
        }
    }
    __syncthreads();

    // ---- vm: scrambled-reshape mean (matches reference raw reshape) --------
    if (tid < BT*F_){
        int bt = tid / F_, j = tid % F_;
        float s = 0.f;
        for (int m=0;m<HW_;m++){
            int flat = j*HW_ + m;
            int fc   = flat % 12;
            int r180 = flat % 180;
            int nn   = (flat/180)*15 + (r180/12);
            s += v_s[bt][fc][nn];
        }
        vm_s[bt][j] = s * (1.0f/HW_);
    }
    __syncthreads();

    // ---- softmax over f=12, one thread per batch ---------------------------
    if (tid < BT){
        int bt = tid;
        float mx = vm_s[bt][0];
        #pragma unroll
        for (int j=1;j<12;j++) mx = fmaxf(mx, vm_s[bt][j]);
        float e[12], ssum = 0.f;
        #pragma unroll
        for (int j=0;j<12;j++){ e[j] = __expf(vm_s[bt][j]-mx); ssum += e[j]; }
        float inv = 1.0f/ssum;
        #pragma unroll
        for (int j=0;j<12;j++) vs_s[bt][j] = e[j]*inv;
    }
    __syncthreads();

    // ---- u[bt][i] = sum_l vs[bt][l] * w41[i,l] -----------------------------
    if (tid < BT*FR_){
        int bt = tid / FR_, i = tid % FR_;
        float u = 0.f;
        #pragma unroll
        for (int l=0;l<12;l++) u = fmaf(vs_s[bt][l], w41[i*12+l], u);
        u_s[bt][i] = u;
    }
    __syncthreads();

    // ---- per-batch: p[c], d[c] and deterministic reductions ----------------
    for (int bt=0;bt<BT;bt++){
        float p = 0.f, d = 0.f;
        if (tid < C_){
            #pragma unroll
            for (int i=0;i<6;i++){
                float wv = w42[tid*6+i];
                p = fmaf(u_s[bt][i], wv, p);
                d = fmaf(b41[i],     wv, d);
            }
            d += b42[tid];
        }
        float s0 = p, s1 = p*p, s2 = p*d, s3 = d;
        #pragma unroll
        for (int o=16;o>0;o>>=1){
            s0 += __shfl_down_sync(0xffffffffu, s0, o);
            s1 += __shfl_down_sync(0xffffffffu, s1, o);
            s2 += __shfl_down_sync(0xffffffffu, s2, o);
            s3 += __shfl_down_sync(0xffffffffu, s3, o);
        }
        int wid = tid >> 5;
        if ((tid & 31) == 0){
            wred[wid][0]=s0; wred[wid][1]=s1; wred[wid][2]=s2; wred[wid][3]=s3;
        }
        __syncthreads();
        if (tid == 0){
            float t0=0,t1=0,t2=0,t3=0;
            #pragma unroll
            for (int w=0;w<8;w++){ t0+=wred[w][0]; t1+=wred[w][1]; t2+=wred[w][2]; t3+=wred[w][3]; }
            tot[0]=t0; tot[1]=t1; tot[2]=t2; tot[3]=t3;
        }
        __syncthreads();
        float mp = tot[0]*(1.0f/C_);
        float md = tot[3]*(1.0f/C_);
        if (tid < C_) g_pp[(b0+bt)*C_ + tid] = p - mp;
        if (tid == 0){
            g_sc[2*(b0+bt)]   = tot[1]*(1.0f/C_) - mp*mp;   // Vp
            g_sc[2*(b0+bt)+1] = tot[2]*(1.0f/C_) - mp*md;   // Cpd
        }
        __syncthreads();
    }
}

// ============================================================================
// K2: elementwise, linear indexing. out[i] = x / (1 + exp(-relu(ln(...))))
// with closed-form LN stats; per-n (a*rs, rs) hoisted to smem.
// ============================================================================
__global__ __launch_bounds__(256, 8) void k2_kernel(
    const float* __restrict__ X,
    const float* __restrict__ b41, const float* __restrict__ w42,
    const float* __restrict__ b42, const float* __restrict__ ln_g,
    const float* __restrict__ ln_b, float* __restrict__ out)
{
    __shared__ float4 cdat[C_];          // {pp*g, (d-md)*g, ln_b, -} per channel
    __shared__ float2 ans[HW_];          // {a*rs, rs} per spatial column
    __shared__ float wred[8][2];
    __shared__ float tot2[2];

    const int tid = threadIdx.x;
    const int b   = blockIdx.x;

    // d[c] (batch-independent) and its stats, deterministically
    float pp = 0.f, d = 0.f;
    if (tid < C_){
        pp = g_pp[b*C_ + tid];
        #pragma unroll
        for (int i=0;i<6;i++) d = fmaf(b41[i], w42[tid*6+i], d);
        d += b42[tid];
    }
    float s0 = d, s1 = d*d;
    #pragma unroll
    for (int o=16;o>0;o>>=1){
        s0 += __shfl_down_sync(0xffffffffu, s0, o);
        s1 += __shfl_down_sync(0xffffffffu, s1, o);
    }
    int wid = tid >> 5;
    if ((tid & 31) == 0){ wred[wid][0]=s0; wred[wid][1]=s1; }
    __syncthreads();
    if (tid == 0){
        float t0=0,t1=0;
        #pragma unroll
        for (int w=0;w<8;w++){ t0+=wred[w][0]; t1+=wred[w][1]; }
        tot2[0]=t0; tot2[1]=t1;
    }
    __syncthreads();
    float md = tot2[0]*(1.0f/C_);
    float Vd = tot2[1]*(1.0f/C_) - md*md;
    if (tid < C_){
        float g = ln_g[tid];
        cdat[tid] = make_float4(pp*g, (d-md)*g, ln_b[tid], 0.f);
    }
    if (tid < HW_){
        float Vp  = g_sc[2*b];
        float Cpd = g_sc[2*b+1];
        float a   = g_kqs[b*HW_ + tid];
        float var = fmaf(a, fmaf(a, Vp, 2.0f*Cpd), Vd) + 1e-5f;
        float rs  = rsqrtf(var);
        ans[tid]  = make_float2(a*rs, rs);
    }
    __syncthreads();

    const float* xb = X   + (size_t)b*NELEM;
    float*       ob = out + (size_t)b*NELEM;
    #pragma unroll 4
    for (int i = tid; i < NELEM; i += 256){
        unsigned ui = (unsigned)i;
        unsigned c  = ui / 225u;
        unsigned nn = ui - 225u*c;
        float  x  = __ldcs(xb + i);
        float4 cd = cdat[c];
        float2 an = ans[nn];
        float t = fmaf(cd.x, an.x, fmaf(cd.y, an.y, cd.z));
        t = fmaxf(t, 0.f);
        float e = __expf(-t);
        ob[i] = __fdividef(x, 1.0f + e);
    }
}

// ============================================================================
extern "C" void kernel_launch(void* const* d_in, const int* in_sizes, int n_in,
                              void* d_out, int out_size)
{
    const float* X    = (const float*)d_in[0];
    const float* w11  = (const float*)d_in[1];
    const float* b11  = (const float*)d_in[2];
    const float* w21  = (const float*)d_in[3];
    const float* b21  = (const float*)d_in[4];
    const float* w31  = (const float*)d_in[5];
    const float* b31  = (const float*)d_in[6];
    const float* w41  = (const float*)d_in[7];
    const float* b41  = (const float*)d_in[8];
    const float* w42  = (const float*)d_in[9];
    const float* b42  = (const float*)d_in[10];
    const float* ln_g = (const float*)d_in[11];
    const float* ln_b = (const float*)d_in[12];
    float* out = (float*)d_out;

    const int dyn_smem = 32000 + BT*F_*232*4;   // 76544 bytes
    cudaFuncSetAttribute(k1_kernel, cudaFuncAttributeMaxDynamicSharedMemorySize, dyn_smem);

    k1_kernel<<<B_/BT, 256, dyn_smem>>>(X, w11,b11, w21,b21, w31,b31, w41,b41, w42,b42);
    k2_kernel<<<B_, 256>>>(X, b41, w42, b42, ln_g, ln_b, out);
}

// round 4
// speedup vs baseline: 1.1033x; 1.1033x over previous
#include <cuda_runtime.h>

typedef unsigned long long u64;

#define B_    1024
#define C_    200
#define HW_   225
#define F_    12
#define FR_   6
#define NELEM (C_*HW_)   /* 45000 */
#define BT    4          /* batches per K1 block */

// ---------------- scratch (static device arrays; no allocation) -------------
__device__ float  g_pp  [B_*C_];    // p[b][c] - mean_c(p[b])
__device__ float2 g_an  [B_*HW_];   // {a*rs, rs} per (b,n)
__device__ float4 g_ctab[C_];       // {ln_g, (d-md)*ln_g, ln_b, 0} per channel
__device__ float  g_dstat[4];       // [0] = Vd

// ---------------- packed-f32 helpers ---------------------------------------
__device__ __forceinline__ u64 pk2(float lo, float hi){
    u64 r; asm("mov.b64 %0, {%1,%2};" : "=l"(r) : "f"(lo), "f"(hi)); return r;
}
__device__ __forceinline__ void upk2(u64 v, float &lo, float &hi){
    asm("mov.b64 {%0,%1}, %2;" : "=f"(lo), "=f"(hi) : "l"(v));
}
__device__ __forceinline__ u64 fma2(u64 a, u64 b, u64 c){
    u64 d; asm("fma.rn.f32x2 %0, %1, %2, %3;" : "=l"(d) : "l"(a), "l"(b), "l"(c));
    return d;
}

// ============================================================================
// K0: one block. Batch-independent d[c] stats + per-channel table.
// ============================================================================
__global__ __launch_bounds__(256, 1) void k0_kernel(
    const float* __restrict__ b41, const float* __restrict__ w42,
    const float* __restrict__ b42, const float* __restrict__ ln_g,
    const float* __restrict__ ln_b)
{
    __shared__ float wred[8][2];
    __shared__ float tot[2];
    const int tid = threadIdx.x;

    float d = 0.f;
    if (tid < C_){
        #pragma unroll
        for (int i=0;i<6;i++) d = fmaf(b41[i], w42[tid*6+i], d);
        d += b42[tid];
    }
    float s0 = d, s1 = d*d;
    #pragma unroll
    for (int o=16;o>0;o>>=1){
        s0 += __shfl_down_sync(0xffffffffu, s0, o);
        s1 += __shfl_down_sync(0xffffffffu, s1, o);
    }
    if ((tid & 31) == 0){ wred[tid>>5][0]=s0; wred[tid>>5][1]=s1; }
    __syncthreads();
    if (tid == 0){
        float t0=0,t1=0;
        #pragma unroll
        for (int w=0;w<8;w++){ t0+=wred[w][0]; t1+=wred[w][1]; }
        tot[0]=t0; tot[1]=t1;
    }
    __syncthreads();
    float md = tot[0]*(1.0f/C_);
    float Vd = tot[1]*(1.0f/C_) - md*md;
    if (tid == 0) g_dstat[0] = Vd;
    if (tid < C_){
        float g = ln_g[tid];
        g_ctab[tid] = make_float4(g, (d - md)*g, ln_b[tid], 0.f);
    }
}

// ============================================================================
// K1: block = 4 batches. GEMM k/q/v with 2-deep X prefetch; epilogue writes
// g_pp and g_an (closed-form LN scalars).
// ============================================================================
__global__ __launch_bounds__(256, 1) void k1_kernel(
    const float* __restrict__ X,
    const float* __restrict__ w11, const float* __restrict__ b11,
    const float* __restrict__ w21, const float* __restrict__ b21,
    const float* __restrict__ w31, const float* __restrict__ b31,
    const float* __restrict__ w41, const float* __restrict__ b41,
    const float* __restrict__ w42, const float* __restrict__ b42)
{
    extern __shared__ __align__(16) unsigned char dynsm[];
    u64   (*wpk)[20]       = (u64 (*)[20])dynsm;                  // [200][20], 32000 B
    float (*v_s)[F_][232]  = (float (*)[F_][232])(dynsm + 32000); // [4][12][232]

    __shared__ float kqs_s[BT][HW_];
    __shared__ float vm_s[BT][F_], vs_s[BT][F_], u_s[BT][FR_];
    __shared__ float wred[8][4];
    __shared__ float tot[4];

    const int tid = threadIdx.x;
    const int b0  = blockIdx.x * BT;

    // ---- pack weights into smem: wpk[c][j] = (w[2j][c], w[2j+1][c]) --------
    for (int idx = tid; idx < C_*18; idx += 256){
        int c = idx/18, j = idx%18;
        int role = j/6, jj = j%6;
        const float* w = (role==0) ? w11 : (role==1) ? w21 : w31;
        wpk[c][j] = pk2(w[(2*jj)*C_ + c], w[(2*jj+1)*C_ + c]);
    }
    __syncthreads();

    // ---- GEMM: thread owns spatial column n for 4 batches ------------------
    const int n = (tid < HW_) ? tid : (HW_-1);
    const float* xp = X + (size_t)b0*NELEM + n;

    u64 acc[BT][18];
    #pragma unroll
    for (int bt=0;bt<BT;bt++)
        #pragma unroll
        for (int j=0;j<18;j++) acc[bt][j] = 0ULL;

    // prefetch buffers: raw floats for c and c+1
    float f0[BT], f1[BT];
    #pragma unroll
    for (int bt=0;bt<BT;bt++){
        f0[bt] = xp[bt*NELEM];
        f1[bt] = xp[bt*NELEM + HW_];
    }
    xp += 2*HW_;

    #pragma unroll 1
    for (int c=0;c<C_;c+=2){
        u64 xx0[BT], xx1[BT];
        #pragma unroll
        for (int bt=0;bt<BT;bt++){ xx0[bt] = pk2(f0[bt], f0[bt]); xx1[bt] = pk2(f1[bt], f1[bt]); }

        // prefetch c+2, c+3 (issued before the FMA block; consumed next iter)
        if (c+2 < C_){
            #pragma unroll
            for (int bt=0;bt<BT;bt++){
                f0[bt] = xp[bt*NELEM];
                f1[bt] = xp[bt*NELEM + HW_];
            }
            xp += 2*HW_;
        }

        const u64* wr0 = wpk[c];
        #pragma unroll
        for (int m=0;m<9;m++){
            ulonglong2 w2 = *reinterpret_cast<const ulonglong2*>(wr0 + 2*m);
            #pragma unroll
            for (int bt=0;bt<BT;bt++){
                acc[bt][2*m]   = fma2(w2.x, xx0[bt], acc[bt][2*m]);
                acc[bt][2*m+1] = fma2(w2.y, xx0[bt], acc[bt][2*m+1]);
            }
        }
        const u64* wr1 = wpk[c+1];
        #pragma unroll
        for (int m=0;m<9;m++){
            ulonglong2 w2 = *reinterpret_cast<const ulonglong2*>(wr1 + 2*m);
            #pragma unroll
            for (int bt=0;bt<BT;bt++){
                acc[bt][2*m]   = fma2(w2.x, xx1[bt], acc[bt][2*m]);
                acc[bt][2*m+1] = fma2(w2.y, xx1[bt], acc[bt][2*m+1]);
            }
        }
    }

    // ---- epilogue: biases, kqs, store v ------------------------------------
    if (tid < HW_){
        #pragma unroll
        for (int bt=0;bt<BT;bt++){
            float kv[12], qv[12], vv[12];
            #pragma unroll
            for (int j=0;j<6;j++){
                upk2(acc[bt][j],    kv[2*j], kv[2*j+1]);
                upk2(acc[bt][6+j],  qv[2*j], qv[2*j+1]);
                upk2(acc[bt][12+j], vv[2*j], vv[2*j+1]);
            }
            float kqs = 0.f;
            #pragma unroll
            for (int f=0; f<12; f++){
                float kf = kv[f] + b11[f];
                float qf = qv[f] + b21[f];
                kqs = fmaf(kf, qf, kqs);
                v_s[bt][f][n] = vv[f] + b31[f];
            }
            kqs_s[bt][n] = kqs;
        }
    }
    __syncthreads();

    // ---- vm: scrambled-reshape mean (matches reference raw reshape) --------
    if (tid < BT*F_){
        int bt = tid / F_, j = tid % F_;
        float s = 0.f;
        for (int m=0;m<HW_;m++){
            int flat = j*HW_ + m;
            int fc   = flat % 12;
            int r180 = flat % 180;
            int nn   = (flat/180)*15 + (r180/12);
            s += v_s[bt][fc][nn];
        }
        vm_s[bt][j] = s * (1.0f/HW_);
    }
    __syncthreads();

    // ---- softmax over f=12, one thread per batch ---------------------------
    if (tid < BT){
        int bt = tid;
        float mx = vm_s[bt][0];
        #pragma unroll
        for (int j=1;j<12;j++) mx = fmaxf(mx, vm_s[bt][j]);
        float e[12], ssum = 0.f;
        #pragma unroll
        for (int j=0;j<12;j++){ e[j] = __expf(vm_s[bt][j]-mx); ssum += e[j]; }
        float inv = 1.0f/ssum;
        #pragma unroll
        for (int j=0;j<12;j++) vs_s[bt][j] = e[j]*inv;
    }
    __syncthreads();

    // ---- u[bt][i] = sum_l vs[bt][l] * w41[i,l] -----------------------------
    if (tid < BT*FR_){
        int bt = tid / FR_, i = tid % FR_;
        float u = 0.f;
        #pragma unroll
        for (int l=0;l<12;l++) u = fmaf(vs_s[bt][l], w41[i*12+l], u);
        u_s[bt][i] = u;
    }
    __syncthreads();

    const float Vd = g_dstat[0];

    // ---- per-batch: p[c], d[c], reductions, then g_pp / g_an ---------------
    for (int bt=0;bt<BT;bt++){
        float p = 0.f, d = 0.f;
        if (tid < C_){
            #pragma unroll
            for (int i=0;i<6;i++){
                float wv = w42[tid*6+i];
                p = fmaf(u_s[bt][i], wv, p);
                d = fmaf(b41[i],     wv, d);
            }
            d += b42[tid];
        }
        float s0 = p, s1 = p*p, s2 = p*d, s3 = d;
        #pragma unroll
        for (int o=16;o>0;o>>=1){
            s0 += __shfl_down_sync(0xffffffffu, s0, o);
            s1 += __shfl_down_sync(0xffffffffu, s1, o);
            s2 += __shfl_down_sync(0xffffffffu, s2, o);
            s3 += __shfl_down_sync(0xffffffffu, s3, o);
        }
        int wid = tid >> 5;
        if ((tid & 31) == 0){
            wred[wid][0]=s0; wred[wid][1]=s1; wred[wid][2]=s2; wred[wid][3]=s3;
        }
        __syncthreads();
        if (tid == 0){
            float t0=0,t1=0,t2=0,t3=0;
            #pragma unroll
            for (int w=0;w<8;w++){ t0+=wred[w][0]; t1+=wred[w][1]; t2+=wred[w][2]; t3+=wred[w][3]; }
            tot[0]=t0; tot[1]=t1; tot[2]=t2; tot[3]=t3;
        }
        __syncthreads();
        float mp = tot[0]*(1.0f/C_);
        float md = tot[3]*(1.0f/C_);
        float Vp  = tot[1]*(1.0f/C_) - mp*mp;
        float Cpd = tot[2]*(1.0f/C_) - mp*md;
        if (tid < C_) g_pp[(b0+bt)*C_ + tid] = p - mp;
        if (tid < HW_){
            float a   = kqs_s[bt][tid];
            float var = fmaf(a, fmaf(a, Vp, 2.0f*Cpd), Vd) + 1e-5f;
            float rs  = rsqrtf(var);
            g_an[(b0+bt)*HW_ + tid] = make_float2(a*rs, rs);
        }
        __syncthreads();
    }
}

// ============================================================================
// K2: pure elementwise from tables. grid = B*2 (batch x channel-half).
// Warp-per-channel, lanes over n. No smem, no sync, no division.
// ============================================================================
__global__ __launch_bounds__(256, 8) void k2_kernel(
    const float* __restrict__ X, float* __restrict__ out)
{
    const int b    = blockIdx.x >> 1;
    const int c0   = (blockIdx.x & 1) * 100;
    const int wid  = threadIdx.x >> 5;
    const int lid  = threadIdx.x & 31;

    const float*  xb  = X   + (size_t)b*NELEM;
    float*        ob  = out + (size_t)b*NELEM;
    const float2* anb = g_an + b*HW_;
    const float*  ppb = g_pp + b*C_;

    for (int c = c0 + wid; c < c0 + 100; c += 8){
        float  pp = __ldg(ppb + c);
        float4 ct = g_ctab[c];
        float Ac = pp*ct.x, Bc = ct.y, Ec = ct.z;
        const float* xr = xb + c*HW_;
        float*       orow = ob + c*HW_;
        #pragma unroll
        for (int j=0;j<8;j++){
            int nn = lid + 32*j;
            if (nn < HW_){
                float2 an = anb[nn];
                float  x  = xr[nn];
                float t = fmaf(an.x, Ac, fmaf(an.y, Bc, Ec));
                t = fmaxf(t, 0.f);
                float e = __expf(-t);
                orow[nn] = __fdividef(x, 1.0f + e);
            }
        }
    }
}

// ============================================================================
extern "C" void kernel_launch(void* const* d_in, const int* in_sizes, int n_in,
                              void* d_out, int out_size)
{
    const float* X    = (const float*)d_in[0];
    const float* w11  = (const float*)d_in[1];
    const float* b11  = (const float*)d_in[2];
    const float* w21  = (const float*)d_in[3];
    const float* b21  = (const float*)d_in[4];
    const float* w31  = (const float*)d_in[5];
    const float* b31  = (const float*)d_in[6];
    const float* w41  = (const float*)d_in[7];
    const float* b41  = (const float*)d_in[8];
    const float* w42  = (const float*)d_in[9];
    const float* b42  = (const float*)d_in[10];
    const float* ln_g = (const float*)d_in[11];
    const float* ln_b = (const float*)d_in[12];
    float* out = (float*)d_out;

    const int dyn_smem = 32000 + BT*F_*232*4;   // 76544 bytes
    cudaFuncSetAttribute(k1_kernel, cudaFuncAttributeMaxDynamicSharedMemorySize, dyn_smem);

    k0_kernel<<<1, 256>>>(b41, w42, b42, ln_g, ln_b);
    k1_kernel<<<B_/BT, 256, dyn_smem>>>(X, w11,b11, w21,b21, w31,b31, w41,b41, w42,b42);
    k2_kernel<<<B_*2, 256>>>(X, out);
}

// round 5
// speedup vs baseline: 1.3736x; 1.2450x over previous
#include <cuda_runtime.h>

typedef unsigned long long u64;

#define B_    1024
#define C_    200
#define HW_   225
#define F_    12
#define FR_   6
#define NELEM (C_*HW_)   /* 45000 */
#define BT    4          /* batches per K1 block */
#define CCH   8          /* channels per staged chunk */
#define NCHK  (C_/CCH)   /* 25 chunks */

// ---------------- scratch (static device arrays; no allocation) -------------
__device__ float  g_pp  [B_*C_];    // p[b][c] - mean_c(p[b])
__device__ float2 g_an  [B_*HW_];   // {a*rs, rs} per (b,n)
__device__ float4 g_ctab[C_];       // {ln_g, (d-md)*ln_g, ln_b, 0} per channel

// ---------------- packed-f32 helpers ---------------------------------------
__device__ __forceinline__ u64 pk2(float lo, float hi){
    u64 r; asm("mov.b64 %0, {%1,%2};" : "=l"(r) : "f"(lo), "f"(hi)); return r;
}
__device__ __forceinline__ void upk2(u64 v, float &lo, float &hi){
    asm("mov.b64 {%0,%1}, %2;" : "=f"(lo), "=f"(hi) : "l"(v));
}
__device__ __forceinline__ u64 fma2(u64 a, u64 b, u64 c){
    u64 d; asm("fma.rn.f32x2 %0, %1, %2, %3;" : "=l"(d) : "l"(a), "l"(b), "l"(c));
    return d;
}
__device__ __forceinline__ void cpa4(unsigned dst, const float* src){
    asm volatile("cp.async.ca.shared.global [%0], [%1], 4;" :: "r"(dst), "l"(src));
}
__device__ __forceinline__ void cpa_commit(){
    asm volatile("cp.async.commit_group;" ::: "memory");
}
template<int N> __device__ __forceinline__ void cpa_wait(){
    asm volatile("cp.async.wait_group %0;" :: "n"(N) : "memory");
}

// smem layout offsets (bytes)
#define SM_WPK   0                        /* u64[200][18]  = 28800 */
#define SM_XS    28800                    /* float[2][7200]= 57600 */
#define SM_VS    86400                    /* float[4][12][232] = 44544 */
#define SM_KQS   130944                   /* float[4][225] = 3600 */
#define SM_TOTAL 134560

// ============================================================================
// K1: block = 4 batches. cp.async double-buffered X staging; GEMM k/q/v from
// smem; epilogue: vm scramble, softmax, u, p/d reductions -> g_pp, g_an.
// Block 0 also writes g_ctab (per-channel LN table for K2).
// ============================================================================
__global__ __launch_bounds__(256, 1) void k1_kernel(
    const float* __restrict__ X,
    const float* __restrict__ w11, const float* __restrict__ b11,
    const float* __restrict__ w21, const float* __restrict__ b21,
    const float* __restrict__ w31, const float* __restrict__ b31,
    const float* __restrict__ w41, const float* __restrict__ b41,
    const float* __restrict__ w42, const float* __restrict__ b42,
    const float* __restrict__ ln_g, const float* __restrict__ ln_b)
{
    extern __shared__ __align__(16) unsigned char dynsm[];
    u64*   wpk   = (u64*)(dynsm + SM_WPK);                    // [200][18]
    float* xs    = (float*)(dynsm + SM_XS);                   // [2][7200]
    float (*v_s)[F_][232] = (float (*)[F_][232])(dynsm + SM_VS);
    float (*kqs_s)[HW_]   = (float (*)[HW_])(dynsm + SM_KQS);

    __shared__ float vm_s[BT][F_], vs_s[BT][F_], u_s[BT][FR_];
    __shared__ float wred[8][5];
    __shared__ float tot[5];
    __shared__ float sh_Vd;

    const int tid = threadIdx.x;
    const int b0  = blockIdx.x * BT;

    const unsigned xs_base = (unsigned)__cvta_generic_to_shared(xs);

    // ---- pack weights into smem: wpk[c][j] = (w[2j][c], w[2j+1][c]) --------
    for (int idx = tid; idx < C_*18; idx += 256){
        int c = idx/18, j = idx%18;
        int role = j/6, jj = j%6;
        const float* w = (role==0) ? w11 : (role==1) ? w21 : w31;
        wpk[c*18 + j] = pk2(w[(2*jj)*C_ + c], w[(2*jj+1)*C_ + c]);
    }

    // ---- staging lambda: chunk ch -> buffer buf ----------------------------
    const int s_cp  = tid & 63;         // 0..63  (n stepping)
    const int bt_cp = tid >> 6;         // 0..3
    const float* xsrc_b = X + (size_t)(b0 + bt_cp)*NELEM;

    auto stage = [&](int ch, int buf){
        const float* src = xsrc_b + (ch*CCH)*HW_;
        unsigned dst0 = xs_base + (unsigned)(buf*7200 + bt_cp*HW_)*4u;
        #pragma unroll
        for (int cc=0; cc<CCH; cc++){
            #pragma unroll
            for (int r=0;r<4;r++){
                int n = s_cp + 64*r;
                if (n < HW_) cpa4(dst0 + (unsigned)(cc*900 + n)*4u, src + cc*HW_ + n);
            }
        }
        cpa_commit();
    };

    stage(0, 0);
    stage(1, 1);
    __syncthreads();   // wpk ready (staging is async; barrier covers weight STS)

    // ---- GEMM main loop ----------------------------------------------------
    const int n = (tid < HW_) ? tid : (HW_-1);

    u64 acc[BT][18];
    #pragma unroll
    for (int bt=0;bt<BT;bt++)
        #pragma unroll
        for (int j=0;j<18;j++) acc[bt][j] = 0ULL;

    #pragma unroll 1
    for (int ch=0; ch<NCHK; ch++){
        cpa_wait<1>();
        __syncthreads();                 // chunk ch visible to all threads

        const int    buf = ch & 1;
        const float* xb  = xs + buf*7200 + n;
        const u64*   wr  = wpk + (ch*CCH)*18;

        #pragma unroll
        for (int cc=0; cc<CCH; cc++){
            u64 xx[BT];
            #pragma unroll
            for (int bt=0;bt<BT;bt++){
                float x = xb[cc*900 + bt*HW_];
                xx[bt] = pk2(x, x);
            }
            #pragma unroll
            for (int m=0;m<9;m++){
                ulonglong2 w2 = *reinterpret_cast<const ulonglong2*>(wr + cc*18 + 2*m);
                #pragma unroll
                for (int bt=0;bt<BT;bt++){
                    acc[bt][2*m]   = fma2(w2.x, xx[bt], acc[bt][2*m]);
                    acc[bt][2*m+1] = fma2(w2.y, xx[bt], acc[bt][2*m+1]);
                }
            }
        }

        __syncthreads();                 // everyone done reading buf
        if (ch+2 < NCHK) stage(ch+2, buf);
    }

    // ---- epilogue: biases, kqs, store v ------------------------------------
    if (tid < HW_){
        #pragma unroll
        for (int bt=0;bt<BT;bt++){
            float kv[12], qv[12], vv[12];
            #pragma unroll
            for (int j=0;j<6;j++){
                upk2(acc[bt][j],    kv[2*j], kv[2*j+1]);
                upk2(acc[bt][6+j],  qv[2*j], qv[2*j+1]);
                upk2(acc[bt][12+j], vv[2*j], vv[2*j+1]);
            }
            float kqs = 0.f;
            #pragma unroll
            for (int f=0; f<12; f++){
                float kf = kv[f] + b11[f];
                float qf = qv[f] + b21[f];
                kqs = fmaf(kf, qf, kqs);
                v_s[bt][f][n] = vv[f] + b31[f];
            }
            kqs_s[bt][n] = kqs;
        }
    }
    __syncthreads();

    // ---- vm: scrambled-reshape mean (matches reference raw reshape) --------
    if (tid < BT*F_){
        int bt = tid / F_, j = tid % F_;
        float s = 0.f;
        for (int m=0;m<HW_;m++){
            int flat = j*HW_ + m;
            int fc   = flat % 12;
            int r180 = flat % 180;
            int nn   = (flat/180)*15 + (r180/12);
            s += v_s[bt][fc][nn];
        }
        vm_s[bt][j] = s * (1.0f/HW_);
    }
    __syncthreads();

    // ---- softmax over f=12, one thread per batch ---------------------------
    if (tid < BT){
        int bt = tid;
        float mx = vm_s[bt][0];
        #pragma unroll
        for (int j=1;j<12;j++) mx = fmaxf(mx, vm_s[bt][j]);
        float e[12], ssum = 0.f;
        #pragma unroll
        for (int j=0;j<12;j++){ e[j] = __expf(vm_s[bt][j]-mx); ssum += e[j]; }
        float inv = 1.0f/ssum;
        #pragma unroll
        for (int j=0;j<12;j++) vs_s[bt][j] = e[j]*inv;
    }
    __syncthreads();

    // ---- u[bt][i] = sum_l vs[bt][l] * w41[i,l] -----------------------------
    if (tid < BT*FR_){
        int bt = tid / FR_, i = tid % FR_;
        float u = 0.f;
        #pragma unroll
        for (int l=0;l<12;l++) u = fmaf(vs_s[bt][l], w41[i*12+l], u);
        u_s[bt][i] = u;
    }
    __syncthreads();

    // ---- per-batch: p[c], d[c], reductions, then g_pp / g_an ---------------
    float Vd = 0.f;
    for (int bt=0;bt<BT;bt++){
        float p = 0.f, d = 0.f;
        if (tid < C_){
            #pragma unroll
            for (int i=0;i<6;i++){
                float wv = w42[tid*6+i];
                p = fmaf(u_s[bt][i], wv, p);
                d = fmaf(b41[i],     wv, d);
            }
            d += b42[tid];
        }
        float s0 = p, s1 = p*p, s2 = p*d, s3 = d, s4 = d*d;
        #pragma unroll
        for (int o=16;o>0;o>>=1){
            s0 += __shfl_down_sync(0xffffffffu, s0, o);
            s1 += __shfl_down_sync(0xffffffffu, s1, o);
            s2 += __shfl_down_sync(0xffffffffu, s2, o);
            s3 += __shfl_down_sync(0xffffffffu, s3, o);
            s4 += __shfl_down_sync(0xffffffffu, s4, o);
        }
        int wid = tid >> 5;
        if ((tid & 31) == 0){
            wred[wid][0]=s0; wred[wid][1]=s1; wred[wid][2]=s2; wred[wid][3]=s3; wred[wid][4]=s4;
        }
        __syncthreads();
        if (tid == 0){
            float t0=0,t1=0,t2=0,t3=0,t4=0;
            #pragma unroll
            for (int w=0;w<8;w++){ t0+=wred[w][0]; t1+=wred[w][1]; t2+=wred[w][2]; t3+=wred[w][3]; t4+=wred[w][4]; }
            tot[0]=t0; tot[1]=t1; tot[2]=t2; tot[3]=t3; tot[4]=t4;
            if (bt == 0){
                float mdd = t3*(1.0f/C_);
                sh_Vd = t4*(1.0f/C_) - mdd*mdd;
            }
        }
        __syncthreads();
        if (bt == 0) Vd = sh_Vd;
        float mp  = tot[0]*(1.0f/C_);
        float md  = tot[3]*(1.0f/C_);
        float Vp  = tot[1]*(1.0f/C_) - mp*mp;
        float Cpd = tot[2]*(1.0f/C_) - mp*md;
        if (tid < C_){
            g_pp[(b0+bt)*C_ + tid] = p - mp;
            if (bt == 0 && blockIdx.x == 0){
                float g = ln_g[tid];
                g_ctab[tid] = make_float4(g, (d - md)*g, ln_b[tid], 0.f);
            }
        }
        if (tid < HW_){
            float a   = kqs_s[bt][tid];
            float var = fmaf(a, fmaf(a, Vp, 2.0f*Cpd), Vd) + 1e-5f;
            float rs  = rsqrtf(var);
            g_an[(b0+bt)*HW_ + tid] = make_float2(a*rs, rs);
        }
        __syncthreads();
    }
}

// ============================================================================
// K2: pure elementwise from tables. grid = B*2 (batch x channel-half).
// Warp-per-channel, lanes over n. No smem, no sync, no division.
// ============================================================================
__global__ __launch_bounds__(256, 8) void k2_kernel(
    const float* __restrict__ X, float* __restrict__ out)
{
    const int b    = blockIdx.x >> 1;
    const int c0   = (blockIdx.x & 1) * 100;
    const int wid  = threadIdx.x >> 5;
    const int lid  = threadIdx.x & 31;

    const float*  xb  = X   + (size_t)b*NELEM;
    float*        ob  = out + (size_t)b*NELEM;
    const float2* anb = g_an + b*HW_;
    const float*  ppb = g_pp + b*C_;

    for (int c = c0 + wid; c < c0 + 100; c += 8){
        float  pp = __ldg(ppb + c);
        float4 ct = g_ctab[c];
        float Ac = pp*ct.x, Bc = ct.y, Ec = ct.z;
        const float* xr = xb + c*HW_;
        float*       orow = ob + c*HW_;
        #pragma unroll
        for (int j=0;j<8;j++){
            int nn = lid + 32*j;
            if (nn < HW_){
                float2 an = anb[nn];
                float  x  = xr[nn];
                float t = fmaf(an.x, Ac, fmaf(an.y, Bc, Ec));
                t = fmaxf(t, 0.f);
                float e = __expf(-t);
                orow[nn] = __fdividef(x, 1.0f + e);
            }
        }
    }
}

// ============================================================================
extern "C" void kernel_launch(void* const* d_in, const int* in_sizes, int n_in,
                              void* d_out, int out_size)
{
    const float* X    = (const float*)d_in[0];
    const float* w11  = (const float*)d_in[1];
    const float* b11  = (const float*)d_in[2];
    const float* w21  = (const float*)d_in[3];
    const float* b21  = (const float*)d_in[4];
    const float* w31  = (const float*)d_in[5];
    const float* b31  = (const float*)d_in[6];
    const float* w41  = (const float*)d_in[7];
    const float* b41  = (const float*)d_in[8];
    const float* w42  = (const float*)d_in[9];
    const float* b42  = (const float*)d_in[10];
    const float* ln_g = (const float*)d_in[11];
    const float* ln_b = (const float*)d_in[12];
    float* out = (float*)d_out;

    cudaFuncSetAttribute(k1_kernel, cudaFuncAttributeMaxDynamicSharedMemorySize, SM_TOTAL);

    k1_kernel<<<B_/BT, 256, SM_TOTAL>>>(X, w11,b11, w21,b21, w31,b31,
                                        w41,b41, w42,b42, ln_g, ln_b);
    k2_kernel<<<B_*2, 256>>>(X, out);
}